// round 17
// baseline (speedup 1.0000x reference)
#include <cuda_runtime.h>
#include <cuda_fp16.h>
#include <math.h>
#include <stddef.h>
#include <stdint.h>
#include <mma.h>

using namespace nvcuda;

typedef unsigned long long ull;

#define B_ 2
#define L_ 1024
#define D_ 64
#define H_ 8
#define NH_ 512
#define MTOT_ 2048

__device__ __half g_q[B_*H_*L_*D_];
__device__ __half g_k[B_*H_*L_*D_];
__device__ __half g_v[B_*H_*L_*D_];
__device__ __half g_ps[B_*H_*L_*L_];
__device__ __half g_wo[NH_*D_];

// ---------------- cp.async helpers ----------------
__device__ __forceinline__ uint32_t s2u32(const void* p) {
    uint32_t a;
    asm("{ .reg .u64 t; cvta.to.shared.u64 t, %1; cvt.u32.u64 %0, t; }" : "=r"(a) : "l"(p));
    return a;
}
__device__ __forceinline__ void cpa16(uint32_t dst, const void* src) {
    asm volatile("cp.async.ca.shared.global [%0], [%1], 16;" :: "r"(dst), "l"(src));
}
#define CPA_COMMIT() asm volatile("cp.async.commit_group;" ::: "memory")
#define CPA_WAIT0()  asm volatile("cp.async.wait_group 0;" ::: "memory")

typedef wmma::fragment<wmma::matrix_a, 16, 16, 16, __half, wmma::row_major> HFragA;
typedef wmma::fragment<wmma::matrix_b, 16, 16, 16, __half, wmma::col_major> HFragBc;
typedef wmma::fragment<wmma::matrix_b, 16, 16, 16, __half, wmma::row_major> HFragBr;
typedef wmma::fragment<wmma::accumulator, 16, 16, 16, float> HFragC;

// ---------------------------------------------------------------------------
// Merged prologue: init_out / wo->fp16 / proj(fp16 out) / pos-v2 (WMMA)
// Segments by blockIdx.x: [0,128) init, [128,160) wo, [160,928) proj, [928,2976) pos
// ---------------------------------------------------------------------------
struct ProjSmem { float As[64][68];  float Ws[64][68]; };
struct PosSmemV2 {
    __half A[8][16*72];    // per-warp absdiff scratch (16 pairs x 64 d, ldm 72)
    __half PJ[64*72];      // pos_j fp16 tile
    __half PI[16*72];      // pos_i fp16 tile
    __half Wph[64*16];     // Wp [d][h], h padded to 16 with zeros
    float  Cs[8][64*20];   // per-warp C staging (64 jj x 16 h, ldm 20)
    float  bps[8];
};

__global__ __launch_bounds__(256) void prep_kernel(
        const float* __restrict__ q_in, const float* __restrict__ k_in,
        const float* __restrict__ v_in, const float* __restrict__ pos,
        const float* __restrict__ Wq, const float* __restrict__ bq,
        const float* __restrict__ Wk, const float* __restrict__ bk,
        const float* __restrict__ Wv, const float* __restrict__ bv,
        const float* __restrict__ Wp, const float* __restrict__ bp,
        const float* __restrict__ Wo, const float* __restrict__ bo,
        float* __restrict__ out)
{
    extern __shared__ __align__(16) char smem_raw[];
    const int cta = blockIdx.x;
    const int tid = threadIdx.x;

    if (cta < 128) {
        // ---- init_out: out[b,l,n] = bo[n] ----
        int idx = cta * 256 + tid;
        float4 b4 = *(const float4*)&bo[(idx & 15) * 4];
        ((float4*)out)[idx] = b4;
        return;
    }
    if (cta < 160) {
        // ---- Wo -> fp16 ----
        int idx = (cta - 128) * 256 + tid;
        float4 w = ((const float4*)Wo)[idx];
        __half2* dst = (__half2*)&g_wo[idx * 4];
        dst[0] = __floats2half2_rn(w.x, w.y);
        dst[1] = __floats2half2_rn(w.z, w.w);
        return;
    }
    if (cta < 928) {
        // ---- proj: z = 0/1/2 (q/k/v), outputs fp16 (q pre-scaled 1/8) ----
        ProjSmem& s = *reinterpret_cast<ProjSmem*>(smem_raw);
        const int pidx = cta - 160;
        const int bx = pidx & 7;
        const int by = (pidx >> 3) & 31;
        const int z  = pidx >> 8;
        const int tx = tid & 15, ty = tid >> 4;
        const int m0 = by * 64, n0 = bx * 64;

        const float* A    = (z == 0) ? q_in : (z == 1) ? k_in : v_in;
        const float* W    = (z == 0) ? Wq   : (z == 1) ? Wk   : Wv;
        const float* bias = (z == 0) ? bq   : (z == 1) ? bk   : bv;
        __half* C         = (z == 0) ? g_q  : (z == 1) ? g_k  : g_v;
        const float sc    = (z == 0) ? 0.125f : 1.0f;

        for (int idx = tid; idx < 1024; idx += 256) {
            int r = idx >> 4, c = (idx & 15) << 2;
            *(float4*)&s.As[r][c] = *(const float4*)&A[(size_t)(m0 + r) * D_ + c];
            *(float4*)&s.Ws[r][c] = *(const float4*)&W[(size_t)r * NH_ + n0 + c];
        }
        __syncthreads();

        float acc[4][4] = {};
        #pragma unroll 8
        for (int k = 0; k < 64; k++) {
            float a[4];
            #pragma unroll
            for (int i = 0; i < 4; i++) a[i] = s.As[ty*4 + i][k];
            float4 w4 = *(float4*)&s.Ws[k][tx*4];
            float w[4] = {w4.x, w4.y, w4.z, w4.w};
            #pragma unroll
            for (int i = 0; i < 4; i++)
                #pragma unroll
                for (int j = 0; j < 4; j++)
                    acc[i][j] += a[i] * w[j];
        }

        #pragma unroll
        for (int i = 0; i < 4; i++) {
            int m = m0 + ty*4 + i;
            int bb = m >> 10;
            int l  = m & (L_ - 1);
            #pragma unroll
            for (int j = 0; j < 4; j++) {
                int n = n0 + tx*4 + j;
                int hh = n >> 6, d = n & 63;
                C[(((size_t)bb * H_ + hh) * L_ + l) * D_ + d]
                    = __float2half_rn((acc[i][j] + bias[n]) * sc);
            }
        }
        return;
    }

    // ---- pos v2: PS[b,h,i,j] via fp16 absdiff + WMMA h-projection ----
    {
        PosSmemV2& s = *reinterpret_cast<PosSmemV2*>(smem_raw);
        const int pidx = cta - 928;            // 0..2047
        const int jt = pidx & 15;              // 16 j-tiles of 64
        const int it = (pidx >> 4) & 63;       // 64 i-tiles of 16
        const int b  = pidx >> 10;             // 0..1
        const int j0 = jt * 64;
        const int i0 = it * 16;
        const float* pb = pos + (size_t)b * L_ * D_;

        // Stage PJ (64x64), PI (16x64) as fp16, Wp [d][16-padded], bp
        for (int idx = tid; idx < 1024; idx += 256) {
            int r = idx >> 4, c4 = (idx & 15) << 2;
            float4 v = *(const float4*)&pb[(size_t)(j0 + r) * D_ + c4];
            __half2* dst = (__half2*)&s.PJ[r*72 + c4];
            dst[0] = __floats2half2_rn(v.x, v.y);
            dst[1] = __floats2half2_rn(v.z, v.w);
        }
        if (tid < 256) {
            int r = tid >> 4, c4 = (tid & 15) << 2;
            float4 v = *(const float4*)&pb[(size_t)(i0 + r) * D_ + c4];
            __half2* dst = (__half2*)&s.PI[r*72 + c4];
            dst[0] = __floats2half2_rn(v.x, v.y);
            dst[1] = __floats2half2_rn(v.z, v.w);
        }
        for (int idx = tid; idx < 1024; idx += 256) {
            int d = idx >> 4, hh = idx & 15;
            s.Wph[d*16 + hh] = (hh < 8) ? __float2half(Wp[d*H_ + hh]) : __half(0);
        }
        if (tid < 8) s.bps[tid] = bp[tid];
        __syncthreads();

        const int w    = tid >> 5;
        const int lane = tid & 31;
        const int lrow2 = lane >> 1;      // row 0..15 within A tile
        const int lhalf = lane & 1;       // d-half (32 halfs each)

        // Wp B-fragments (row-major, ldm 16), hoisted for the whole kernel
        HFragBr wpB[4];
        #pragma unroll
        for (int kk = 0; kk < 4; kk++)
            wmma::load_matrix_sync(wpB[kk], &s.Wph[kk*16*16], 16);

        __half* Aw = &s.A[w][0];
        float*  Cw = &s.Cs[w][0];

        #pragma unroll
        for (int iiL = 0; iiL < 2; iiL++) {
            const int ii = w*2 + iiL;

            // hoist this lane's PI d-chunk (16 half2)
            __half2 piR[16];
            #pragma unroll
            for (int c = 0; c < 16; c++)
                piR[c] = *(const __half2*)&s.PI[ii*72 + lhalf*32 + 2*c];

            #pragma unroll
            for (int rt = 0; rt < 4; rt++) {
                const int jjb = rt * 16;
                __syncwarp();   // A scratch free (prev rt's frag loads done)
                #pragma unroll
                for (int c = 0; c < 16; c++) {
                    __half2 pj = *(const __half2*)&s.PJ[(jjb + lrow2)*72 + lhalf*32 + 2*c];
                    *(__half2*)&Aw[lrow2*72 + lhalf*32 + 2*c]
                        = __habs2(__hsub2(piR[c], pj));
                }
                __syncwarp();

                HFragC cf;
                wmma::fill_fragment(cf, 0.0f);
                #pragma unroll
                for (int kk = 0; kk < 4; kk++) {
                    HFragA a;
                    wmma::load_matrix_sync(a, &Aw[kk*16], 72);
                    wmma::mma_sync(cf, a, wpB[kk], cf);
                }
                wmma::store_matrix_sync(&Cw[jjb*20], cf, 20, wmma::mem_row_major);
            }
            __syncwarp();   // Cs complete for this ii

            // write out: 8 h rows of 64 jj (coalesced 128B per row)
            #pragma unroll
            for (int hh = 0; hh < 8; hh++) {
                float bpv = s.bps[hh];
                float v0 = Cw[(2*lane)*20 + hh] + bpv;
                float v1 = Cw[(2*lane+1)*20 + hh] + bpv;
                *(__half2*)&g_ps[((size_t)(b*H_ + hh) << 20)
                                 + ((size_t)(i0 + ii) << 10) + j0 + 2*lane]
                    = __floats2half2_rn(v0, v1);
            }
            __syncwarp();   // Cs reusable for next ii
        }
    }
}

// ---------------------------------------------------------------------------
// Attention v5 (unchanged from R16): fp16 WMMA, warp-autonomous rows,
// triple-stream cp.async double buffer (K, V, ps).
// ---------------------------------------------------------------------------
#define LDK 72            // half stride (144 B rows)
#define LDS4 68           // float stride for S

#define KV_H (64*LDK)
#define PS_H (128*LDK)

struct AttnSmemH {
    __half Ks[2][KV_H];
    __half Vs[2][KV_H];
    __half PSs[2][PS_H];
    float  Ss[128*LDS4];
    __half Ph[128*LDK];
};

__device__ __forceinline__ void stage_tile(uint32_t ksm, uint32_t vsm, uint32_t psm,
        const __half* kb, const __half* vb, const __half* ps_t, int j0, int tid)
{
    #pragma unroll
    for (int n = 0; n < 2; n++) {
        int idx = tid + n*256;
        int r = idx >> 3, c = idx & 7;
        uint32_t off = (uint32_t)(r*LDK + c*8) * 2u;
        cpa16(ksm + off, kb + (size_t)(j0 + r) * D_ + c*8);
        cpa16(vsm + off, vb + (size_t)(j0 + r) * D_ + c*8);
    }
    #pragma unroll
    for (int n = 0; n < 4; n++) {
        int idx = tid + n*256;
        int r = idx >> 3, c = idx & 7;
        cpa16(psm + (uint32_t)(r*LDK + c*8)*2u, ps_t + (size_t)r * L_ + c*8);
    }
}

__global__ __launch_bounds__(256) void attn_wmma(float* __restrict__ out)
{
    extern __shared__ char sraw[];
    AttnSmemH& s = *reinterpret_cast<AttnSmemH*>(sraw);

    const int tid  = threadIdx.x;
    const int wid  = tid >> 5;
    const int lane = tid & 31;
    const int row0 = wid * 16;
    const int i0 = blockIdx.x * 128;
    const int h  = blockIdx.y;
    const int b  = blockIdx.z;

    const __half* qb  = g_q  + (size_t)(b*H_ + h) * L_ * D_;
    const __half* kb  = g_k  + (size_t)(b*H_ + h) * L_ * D_;
    const __half* vb  = g_v  + (size_t)(b*H_ + h) * L_ * D_;
    const __half* psb = g_ps + ((size_t)(b*H_ + h) << 20) + ((size_t)i0 << 10);

    const uint32_t sbase = s2u32(sraw);
    const uint32_t ksm0 = sbase + (uint32_t)offsetof(AttnSmemH, Ks);
    const uint32_t ksm1 = ksm0 + sizeof(__half)*KV_H;
    const uint32_t vsm0 = sbase + (uint32_t)offsetof(AttnSmemH, Vs);
    const uint32_t vsm1 = vsm0 + sizeof(__half)*KV_H;
    const uint32_t psm0 = sbase + (uint32_t)offsetof(AttnSmemH, PSs);
    const uint32_t psm1 = psm0 + sizeof(__half)*PS_H;

    stage_tile(ksm0, vsm0, psm0, kb, vb, psb, 0, tid);
    CPA_COMMIT();

    HFragA qf[4];
    #pragma unroll
    for (int kk = 0; kk < 4; kk++)
        wmma::load_matrix_sync(qf[kk], qb + (size_t)(i0 + row0) * D_ + kk*16, D_);

    HFragC accO[4];
    #pragma unroll
    for (int nn = 0; nn < 4; nn++) wmma::fill_fragment(accO[nn], 0.0f);

    float rl = 0.0f;
    float*  Sw = &s.Ss[row0 * LDS4];
    __half* Pw = &s.Ph[row0 * LDK];
    const int lrow = lane >> 1;
    const int lcol = (lane & 1) * 32;

    CPA_WAIT0();
    __syncthreads();

    for (int t = 0; t < 16; t++) {
        const int cur = t & 1;
        const __half* Kp  = &s.Ks[cur][0];
        const __half* Vp  = &s.Vs[cur][0];
        const __half* PSp = &s.PSs[cur][0];

        if (t < 15) {
            stage_tile(cur ? ksm0 : ksm1, cur ? vsm0 : vsm1, cur ? psm0 : psm1,
                       kb, vb, psb + (t+1)*64, (t+1)*64, tid);
            CPA_COMMIT();
        }

        HFragC accS[4];
        #pragma unroll
        for (int nn = 0; nn < 4; nn++) wmma::fill_fragment(accS[nn], 0.0f);
        #pragma unroll
        for (int kk = 0; kk < 4; kk++) {
            #pragma unroll
            for (int nn = 0; nn < 4; nn++) {
                HFragBc kf;
                wmma::load_matrix_sync(kf, &Kp[(nn*16)*LDK + kk*16], LDK);
                wmma::mma_sync(accS[nn], qf[kk], kf, accS[nn]);
            }
        }
        #pragma unroll
        for (int nn = 0; nn < 4; nn++)
            wmma::store_matrix_sync(&Sw[nn*16], accS[nn], LDS4, wmma::mem_row_major);
        __syncwarp();

        {
            const float*  srow = &Sw[lrow*LDS4 + lcol];
            const __half* prow = &PSp[(row0 + lrow)*LDK + lcol];
            __half*       orow = &Pw[lrow*LDK + lcol];
            float sm = 0.0f;
            #pragma unroll
            for (int c = 0; c < 32; c += 2) {
                float2 pf = __half22float2(*(const __half2*)&prow[c]);
                float p0 = __expf(srow[c+0] + pf.x);
                float p1 = __expf(srow[c+1] + pf.y);
                sm += p0 + p1;
                *(__half2*)&orow[c] = __floats2half2_rn(p0, p1);
            }
            sm += __shfl_xor_sync(0xffffffffu, sm, 1);
            rl += sm;
        }
        __syncwarp();

        #pragma unroll
        for (int kk = 0; kk < 4; kk++) {
            HFragA a;
            wmma::load_matrix_sync(a, &Pw[kk*16], LDK);
            #pragma unroll
            for (int nn = 0; nn < 4; nn++) {
                HFragBr vf;
                wmma::load_matrix_sync(vf, &Vp[(kk*16)*LDK + nn*16], LDK);
                wmma::mma_sync(accO[nn], a, vf, accO[nn]);
            }
        }

        if (t < 15) CPA_WAIT0();
        __syncthreads();
    }

    #pragma unroll
    for (int nn = 0; nn < 4; nn++)
        wmma::store_matrix_sync(&Sw[nn*16], accO[nn], LDS4, wmma::mem_row_major);
    __syncwarp();
    {
        const float inv = 1.0f / rl;
        const float* orow = &Sw[lrow*LDS4 + lcol];
        __half* hrow = &Pw[lrow*LDK + lcol];
        #pragma unroll
        for (int c = 0; c < 32; c += 2)
            *(__half2*)&hrow[c] = __floats2half2_rn(orow[c]*inv, orow[c+1]*inv);
    }
    __syncwarp();

    HFragC accR[4];
    #pragma unroll
    for (int nn = 0; nn < 4; nn++) wmma::fill_fragment(accR[nn], 0.0f);
    const __half* wo = g_wo + (size_t)(h*64) * D_;
    #pragma unroll
    for (int kk = 0; kk < 4; kk++) {
        HFragA a;
        wmma::load_matrix_sync(a, &Pw[kk*16], LDK);
        #pragma unroll
        for (int nn = 0; nn < 4; nn++) {
            HFragBr wf;
            wmma::load_matrix_sync(wf, wo + (size_t)(kk*16)*D_ + nn*16, D_);
            wmma::mma_sync(accR[nn], a, wf, accR[nn]);
        }
    }
    __syncwarp();
    #pragma unroll
    for (int nn = 0; nn < 4; nn++)
        wmma::store_matrix_sync(&Sw[nn*16], accR[nn], LDS4, wmma::mem_row_major);
    __syncwarp();
    {
        float* dst = &out[(((size_t)b << 10) + i0 + row0 + lrow) * D_ + lcol];
        const float* src = &Sw[lrow*LDS4 + lcol];
        #pragma unroll
        for (int c = 0; c < 32; c++) atomicAdd(dst + c, src[c]);
    }
}

// ---------------------------------------------------------------------------
extern "C" void kernel_launch(void* const* d_in, const int* in_sizes, int n_in,
                              void* d_out, int out_size)
{
    const float* query = (const float*)d_in[0];
    const float* key   = (const float*)d_in[1];
    const float* value = (const float*)d_in[2];
    const float* pos   = (const float*)d_in[3];
    const float* Wq    = (const float*)d_in[4];
    const float* bq    = (const float*)d_in[5];
    const float* Wk    = (const float*)d_in[6];
    const float* bk    = (const float*)d_in[7];
    const float* Wv    = (const float*)d_in[8];
    const float* bv    = (const float*)d_in[9];
    const float* Wp    = (const float*)d_in[10];
    const float* bp    = (const float*)d_in[11];
    const float* Wo    = (const float*)d_in[12];
    const float* bo    = (const float*)d_in[13];
    float* out = (float*)d_out;

    const int prep_smem = (sizeof(PosSmemV2) > sizeof(ProjSmem))
                        ? (int)sizeof(PosSmemV2) : (int)sizeof(ProjSmem);
    cudaFuncSetAttribute(prep_kernel, cudaFuncAttributeMaxDynamicSharedMemorySize,
                         prep_smem);
    prep_kernel<<<dim3(2976), 256, prep_smem>>>(
        query, key, value, pos, Wq, bq, Wk, bk, Wv, bv, Wp, bp, Wo, bo, out);

    cudaFuncSetAttribute(attn_wmma, cudaFuncAttributeMaxDynamicSharedMemorySize,
                         (int)sizeof(AttnSmemH));
    attn_wmma<<<dim3(L_/128, H_, B_), 256, sizeof(AttnSmemH)>>>(out);
}